// round 3
// baseline (speedup 1.0000x reference)
#include <cuda_runtime.h>
#include <cstdint>

// ---------------------------------------------------------------------------
// Problem dims
// ---------------------------------------------------------------------------
static constexpr int T_ = 8192;   // tokens (M)
static constexpr int O_ = 4096;   // out features (N)
static constexpr int I_ = 4096;   // in features (K)
static constexpr int G_ = I_ / 256;   // 16 groups per row

// ---------------------------------------------------------------------------
// Scratch (device globals — no runtime allocation allowed)
//   g_xq8 : q (int8 code, zero-point NOT subtracted)
//   g_wq8 : (w - z) exact int8 in [-12, 11]
//   g_sx  : per-token activation scale
//   g_zp  : per-token zero point (integral float)
//   g_cs  : colsum[o] = sum_k w_dq[o,k]  (fp32)
// ---------------------------------------------------------------------------
__device__ __align__(16) signed char g_xq8[(size_t)T_ * I_];
__device__ __align__(16) signed char g_wq8[(size_t)O_ * I_];
__device__ float g_sx[T_];
__device__ float g_zp[T_];
__device__ float g_cs[O_];

// ---------------------------------------------------------------------------
// PTX helpers (classic path only — no tcgen05: toolchain targets compute_103)
// ---------------------------------------------------------------------------
__device__ __forceinline__ void cp_async16(uint32_t saddr, const void* gptr) {
    asm volatile("cp.async.cg.shared.global [%0], [%1], 16;\n"
                 :: "r"(saddr), "l"(gptr) : "memory");
}
__device__ __forceinline__ void cp_commit() {
    asm volatile("cp.async.commit_group;\n" ::: "memory");
}
template <int N>
__device__ __forceinline__ void cp_wait() {
    asm volatile("cp.async.wait_group %0;\n" :: "n"(N) : "memory");
}
__device__ __forceinline__ uint32_t smem_u32(const void* p) {
    uint32_t a;
    asm("{ .reg .u64 t; cvta.to.shared.u64 t, %1; cvt.u32.u64 %0, t; }"
        : "=r"(a) : "l"(p));
    return a;
}
__device__ __forceinline__ void ldmatrix_x4(uint32_t (&r)[4], uint32_t addr) {
    asm volatile("ldmatrix.sync.aligned.m8n8.x4.shared.b16 {%0,%1,%2,%3}, [%4];\n"
                 : "=r"(r[0]), "=r"(r[1]), "=r"(r[2]), "=r"(r[3]) : "r"(addr));
}
// int8 tensor-core mma: D(s32) += A(s8,16x32) * B(s8,32x8)
__device__ __forceinline__ void mma_s8(int (&d)[4], const uint32_t (&a)[4],
                                       uint32_t b0, uint32_t b1) {
    asm volatile(
        "mma.sync.aligned.m16n8k32.row.col.s32.s8.s8.s32 "
        "{%0,%1,%2,%3}, {%4,%5,%6,%7}, {%8,%9}, {%0,%1,%2,%3};\n"
        : "+r"(d[0]), "+r"(d[1]), "+r"(d[2]), "+r"(d[3])
        : "r"(a[0]), "r"(a[1]), "r"(a[2]), "r"(a[3]), "r"(b0), "r"(b1));
}

// ---------------------------------------------------------------------------
// Kernel 1: per-token asymmetric int8 fake-quant of x (exact vs reference).
// Stores q (int8) + scale + zero-point.
// ---------------------------------------------------------------------------
__global__ void __launch_bounds__(256) quant_x_kernel(const float* __restrict__ x) {
    const int row = blockIdx.x;
    const int tid = threadIdx.x;
    const float4* xr = reinterpret_cast<const float4*>(x) + (size_t)row * (I_ / 4);

    float4 v[4];
    float mn = 0.0f, mx = 0.0f;
#pragma unroll
    for (int j = 0; j < 4; ++j) {
        v[j] = xr[tid + 256 * j];
        mn = fminf(mn, fminf(fminf(v[j].x, v[j].y), fminf(v[j].z, v[j].w)));
        mx = fmaxf(mx, fmaxf(fmaxf(v[j].x, v[j].y), fmaxf(v[j].z, v[j].w)));
    }
#pragma unroll
    for (int o = 16; o > 0; o >>= 1) {
        mn = fminf(mn, __shfl_xor_sync(0xffffffffu, mn, o));
        mx = fmaxf(mx, __shfl_xor_sync(0xffffffffu, mx, o));
    }
    __shared__ float smn[8], smx[8];
    if ((tid & 31) == 0) { smn[tid >> 5] = mn; smx[tid >> 5] = mx; }
    __syncthreads();
    mn = smn[0]; mx = smx[0];
#pragma unroll
    for (int w = 1; w < 8; ++w) { mn = fminf(mn, smn[w]); mx = fmaxf(mx, smx[w]); }

    const float scale = fmaxf(__fdiv_rn(mx - mn, 255.0f), 1.1920929e-07f);
    const float dmin = __fdiv_rn(mn, scale);
    const float dmax = __fdiv_rn(mx, scale);
    float zp = ((-128.0f + dmin) + (127.0f + dmax) > 0.0f) ? (-128.0f - dmin)
                                                           : (127.0f - dmax);
    zp = rintf(fminf(fmaxf(zp, -128.0f), 127.0f));

    signed char* out = g_xq8 + (size_t)row * I_;
#pragma unroll
    for (int j = 0; j < 4; ++j) {
        float f[4] = {v[j].x, v[j].y, v[j].z, v[j].w};
        char4 c;
        float q0 = fminf(fmaxf(rintf(__fdiv_rn(f[0], scale)) + zp, -128.0f), 127.0f);
        float q1 = fminf(fmaxf(rintf(__fdiv_rn(f[1], scale)) + zp, -128.0f), 127.0f);
        float q2 = fminf(fmaxf(rintf(__fdiv_rn(f[2], scale)) + zp, -128.0f), 127.0f);
        float q3 = fminf(fmaxf(rintf(__fdiv_rn(f[3], scale)) + zp, -128.0f), 127.0f);
        c.x = (signed char)(int)q0;
        c.y = (signed char)(int)q1;
        c.z = (signed char)(int)q2;
        c.w = (signed char)(int)q3;
        *reinterpret_cast<char4*>(out + (size_t)(tid + 256 * j) * 4) = c;
    }
    if (tid == 0) { g_sx[row] = scale; g_zp[row] = zp; }
}

// ---------------------------------------------------------------------------
// Kernel 2: weight repack (w - z) -> int8, plus colsum[o] = sum_k w_dq[o,k].
// One block (256 threads) per output row o; each thread handles 16 elems
// (all within one group of 256).
// ---------------------------------------------------------------------------
__global__ void __launch_bounds__(256) dequant_w_kernel(const int* __restrict__ w,
                                                        const float* __restrict__ scales,
                                                        const float* __restrict__ zeros) {
    const int o = blockIdx.x;
    const int tid = threadIdx.x;
    const int base = tid * 16;
    const int g = tid >> 4;
    const float s = scales[o * G_ + g];
    const int zi = (int)zeros[o * G_ + g];   // zeros are integral floats

    const int4* wp = reinterpret_cast<const int4*>(w + (size_t)o * I_ + base);
    int4 a = wp[0], b = wp[1], c = wp[2], d = wp[3];

    union { uint4 u; signed char q[16]; } pk;
    int vals[16] = {a.x, a.y, a.z, a.w, b.x, b.y, b.z, b.w,
                    c.x, c.y, c.z, c.w, d.x, d.y, d.z, d.w};
    int isum = 0;
#pragma unroll
    for (int e = 0; e < 16; ++e) {
        const int q = vals[e] - zi;          // in [-12, 11]
        pk.q[e] = (signed char)q;
        isum += q;
    }
    *reinterpret_cast<uint4*>(g_wq8 + (size_t)o * I_ + base) = pk.u;

    float ps = s * (float)isum;
#pragma unroll
    for (int off = 16; off > 0; off >>= 1)
        ps += __shfl_xor_sync(0xffffffffu, ps, off);
    __shared__ float red[8];
    if ((tid & 31) == 0) red[tid >> 5] = ps;
    __syncthreads();
    if (tid == 0) {
        float t = 0.0f;
#pragma unroll
        for (int i = 0; i < 8; ++i) t += red[i];
        g_cs[o] = t;
    }
}

// ---------------------------------------------------------------------------
// Kernel 3: int8 IMMA GEMM with per-group fp32 rescale.
//   C[t,o] = sx[t] * ( sum_g s_g[o] * S_g(t,o)  -  zp[t] * colsum[o] )
//   S_g = exact int32 sum of q * (w - z) over the 256-wide group.
// Tile 128x128, BK=128 int8, 3-stage cp.async pipeline, SW-swizzled SMEM,
// 8 warps (2x4), warp tile 64x32 via m16n8k32 s8 mma.
// ---------------------------------------------------------------------------
static constexpr int BM = 128;
static constexpr int BN = 128;
static constexpr int BK = 128;                 // int8 elems per stage (=128B rows)
static constexpr int STAGES = 3;
static constexpr int NUM_KT = I_ / BK;         // 32 stages, group = 2 stages
static constexpr int A_ST = BM * BK;           // 16 KB
static constexpr int ST = 2 * A_ST;            // 32 KB per stage
static constexpr int GEMM_SMEM = STAGES * ST + 1024;

__global__ void __launch_bounds__(256, 1) gemm_kernel(float* __restrict__ C,
                                                      const float* __restrict__ scales) {
    extern __shared__ signed char dsm[];
    const uint32_t sbase = (smem_u32(dsm) + 127u) & ~127u;

    const int tid = threadIdx.x;
    const int lane = tid & 31;
    const int wid = tid >> 5;
    const int wm = wid >> 2;     // 0..1 : 64 rows
    const int wn = wid & 3;      // 0..3 : 32 cols

    const int bn = blockIdx.x & 31;       // 32 N tiles
    const int bm = blockIdx.x >> 5;       // 64 M tiles
    const int m0 = bm * BM;
    const int n0 = bn * BN;

    const signed char* Ag = g_xq8 + (size_t)m0 * I_;
    const signed char* Bg = g_wq8 + (size_t)n0 * I_;

    int   iacc[4][4][4];
    float facc[4][4][4];
#pragma unroll
    for (int a = 0; a < 4; ++a)
#pragma unroll
        for (int b = 0; b < 4; ++b)
#pragma unroll
            for (int c = 0; c < 4; ++c) { iacc[a][b][c] = 0; facc[a][b][c] = 0.0f; }

    // Per-thread output columns (2 per n-fragment), for scale / colsum loads.
    int colbase[4];
#pragma unroll
    for (int ni = 0; ni < 4; ++ni)
        colbase[ni] = n0 + wn * 32 + ni * 8 + (lane & 3) * 2;

    // cp.async producer: all 256 threads, 2048 x 16B chunks per stage.
    auto issue_loads = [&](int s) {
        const int buf = s % STAGES;
        const uint32_t sa = sbase + buf * ST;
        const int kcol = s * BK;
#pragma unroll
        for (int i = 0; i < 8; ++i) {
            const int c = tid + i * 256;
            if (c < 1024) {                      // A: 128 rows x 8 chunks
                const int row = c >> 3, ch = c & 7;
                cp_async16(sa + row * 128 + (((uint32_t)(ch ^ (row & 7))) << 4),
                           Ag + (size_t)row * I_ + kcol + ch * 16);
            } else {                             // B: 128 rows x 8 chunks
                const int c2 = c - 1024;
                const int row = c2 >> 3, ch = c2 & 7;
                cp_async16(sa + A_ST + row * 128 + (((uint32_t)(ch ^ (row & 7))) << 4),
                           Bg + (size_t)row * I_ + kcol + ch * 16);
            }
        }
        cp_commit();
    };

    issue_loads(0);
    issue_loads(1);

    float sc[4][2];   // group scales for this thread's 8 output columns

    for (int s = 0; s < NUM_KT; ++s) {
        if (s + 2 < NUM_KT) issue_loads(s + 2);
        else cp_commit();                        // keep group counts uniform
        cp_wait<2>();                            // stage s resident
        __syncthreads();

        if ((s & 1) == 0) {                      // prefetch scales for group s/2
            const int g = s >> 1;
#pragma unroll
            for (int ni = 0; ni < 4; ++ni) {
                sc[ni][0] = scales[colbase[ni] * G_ + g];
                sc[ni][1] = scales[(colbase[ni] + 1) * G_ + g];
            }
        }

        const uint32_t bA = sbase + (s % STAGES) * ST;
        const uint32_t bB = bA + A_ST;

#pragma unroll
        for (int ks = 0; ks < 4; ++ks) {         // 4 x K=32 per stage
            uint32_t afr[4][4];
#pragma unroll
            for (int mi = 0; mi < 4; ++mi) {
                const uint32_t row = wm * 64 + mi * 16 + (lane & 7) + (lane & 8);
                const uint32_t ch = 2 * ks + ((lane >> 4) & 1);
                ldmatrix_x4(afr[mi], bA + row * 128 + ((ch ^ (row & 7)) << 4));
            }
            uint32_t bfr[2][4];
#pragma unroll
            for (int np = 0; np < 2; ++np) {
                const uint32_t row =
                    wn * 32 + np * 16 + (lane & 7) + (((lane >> 4) & 1) << 3);
                const uint32_t ch = 2 * ks + ((lane >> 3) & 1);
                ldmatrix_x4(bfr[np], bB + row * 128 + ((ch ^ (row & 7)) << 4));
            }
#pragma unroll
            for (int mi = 0; mi < 4; ++mi)
#pragma unroll
                for (int ni = 0; ni < 4; ++ni)
                    mma_s8(iacc[mi][ni], afr[mi],
                           bfr[ni >> 1][(ni & 1) * 2],
                           bfr[ni >> 1][(ni & 1) * 2 + 1]);
        }

        if (s & 1) {                             // group boundary: rescale
#pragma unroll
            for (int mi = 0; mi < 4; ++mi)
#pragma unroll
                for (int ni = 0; ni < 4; ++ni) {
                    facc[mi][ni][0] += (float)iacc[mi][ni][0] * sc[ni][0];
                    facc[mi][ni][1] += (float)iacc[mi][ni][1] * sc[ni][1];
                    facc[mi][ni][2] += (float)iacc[mi][ni][2] * sc[ni][0];
                    facc[mi][ni][3] += (float)iacc[mi][ni][3] * sc[ni][1];
                    iacc[mi][ni][0] = 0; iacc[mi][ni][1] = 0;
                    iacc[mi][ni][2] = 0; iacc[mi][ni][3] = 0;
                }
        }
        __syncthreads();
    }

    // Epilogue: out = sx[t] * (facc - zp[t] * colsum[o])
#pragma unroll
    for (int mi = 0; mi < 4; ++mi) {
        const int r0 = m0 + wm * 64 + mi * 16 + (lane >> 2);
        const int r1 = r0 + 8;
        const float sx0 = g_sx[r0], zp0 = g_zp[r0];
        const float sx1 = g_sx[r1], zp1 = g_zp[r1];
#pragma unroll
        for (int ni = 0; ni < 4; ++ni) {
            const int col = colbase[ni];
            const float cs0 = g_cs[col], cs1 = g_cs[col + 1];
            float2 v0, v1;
            v0.x = sx0 * (facc[mi][ni][0] - zp0 * cs0);
            v0.y = sx0 * (facc[mi][ni][1] - zp0 * cs1);
            v1.x = sx1 * (facc[mi][ni][2] - zp1 * cs0);
            v1.y = sx1 * (facc[mi][ni][3] - zp1 * cs1);
            *reinterpret_cast<float2*>(C + (size_t)r0 * O_ + col) = v0;
            *reinterpret_cast<float2*>(C + (size_t)r1 * O_ + col) = v1;
        }
    }
}

// ---------------------------------------------------------------------------
// Launch
// ---------------------------------------------------------------------------
extern "C" void kernel_launch(void* const* d_in, const int* in_sizes, int n_in,
                              void* d_out, int out_size) {
    const float* x = (const float*)d_in[0];
    const int* w = (const int*)d_in[1];
    const float* scales = (const float*)d_in[2];
    const float* zeros = (const float*)d_in[3];
    float* out = (float*)d_out;

    static bool attr_done = false;
    if (!attr_done) {
        cudaFuncSetAttribute(gemm_kernel,
                             cudaFuncAttributeMaxDynamicSharedMemorySize,
                             GEMM_SMEM);
        attr_done = true;
    }

    quant_x_kernel<<<T_, 256>>>(x);
    dequant_w_kernel<<<O_, 256>>>(w, scales, zeros);
    gemm_kernel<<<(T_ / BM) * (O_ / BN), 256, GEMM_SMEM>>>(out, scales);
}

// round 4
// speedup vs baseline: 3.0371x; 3.0371x over previous
#include <cuda_runtime.h>
#include <cuda_fp16.h>
#include <cstdint>

// ---------------------------------------------------------------------------
// Problem dims
// ---------------------------------------------------------------------------
static constexpr int T_ = 8192;   // tokens (M)
static constexpr int O_ = 4096;   // out features (N)
static constexpr int I_ = 4096;   // in features (K)
static constexpr int G_ = I_ / 256;

// ---------------------------------------------------------------------------
// Scratch (device globals — no runtime allocation allowed)
// ---------------------------------------------------------------------------
__device__ __half g_xq[(size_t)T_ * I_];   // (q - zp), exact integer in fp16
__device__ __half g_wq[(size_t)O_ * I_];   // (w - z) * s in fp16
__device__ float  g_sx[T_];                // per-token activation scale

// ---------------------------------------------------------------------------
// PTX helpers (classic sm_90-style path; tcgen05 unavailable on this toolchain)
// ---------------------------------------------------------------------------
__device__ __forceinline__ void cp_async16(uint32_t saddr, const void* gptr) {
    asm volatile("cp.async.cg.shared.global [%0], [%1], 16;\n"
                 :: "r"(saddr), "l"(gptr) : "memory");
}
__device__ __forceinline__ void cp_commit() {
    asm volatile("cp.async.commit_group;\n" ::: "memory");
}
template <int N>
__device__ __forceinline__ void cp_wait() {
    asm volatile("cp.async.wait_group %0;\n" :: "n"(N) : "memory");
}
__device__ __forceinline__ uint32_t smem_u32(const void* p) {
    uint32_t a;
    asm("{ .reg .u64 t; cvta.to.shared.u64 t, %1; cvt.u32.u64 %0, t; }"
        : "=r"(a) : "l"(p));
    return a;
}
__device__ __forceinline__ void ldmatrix_x4(uint32_t (&r)[4], uint32_t addr) {
    asm volatile("ldmatrix.sync.aligned.m8n8.x4.shared.b16 {%0,%1,%2,%3}, [%4];\n"
                 : "=r"(r[0]), "=r"(r[1]), "=r"(r[2]), "=r"(r[3]) : "r"(addr));
}
__device__ __forceinline__ void mma16816(float (&d)[4], const uint32_t (&a)[4],
                                         uint32_t b0, uint32_t b1) {
    asm volatile(
        "mma.sync.aligned.m16n8k16.row.col.f32.f16.f16.f32 "
        "{%0,%1,%2,%3}, {%4,%5,%6,%7}, {%8,%9}, {%0,%1,%2,%3};\n"
        : "+f"(d[0]), "+f"(d[1]), "+f"(d[2]), "+f"(d[3])
        : "r"(a[0]), "r"(a[1]), "r"(a[2]), "r"(a[3]), "r"(b0), "r"(b1));
}

// ---------------------------------------------------------------------------
// Kernel 1: per-token asymmetric int8 fake-quant of x (bit-exact vs reference).
// Stores (q - zp) as fp16 (exact integer in [-255,255]) and sx per row.
// ---------------------------------------------------------------------------
__global__ void __launch_bounds__(256) quant_x_kernel(const float* __restrict__ x) {
    const int row = blockIdx.x;
    const int tid = threadIdx.x;
    const float4* xr = reinterpret_cast<const float4*>(x) + (size_t)row * (I_ / 4);

    float4 v[4];
    float mn = 0.0f, mx = 0.0f;
#pragma unroll
    for (int j = 0; j < 4; ++j) {
        v[j] = xr[tid + 256 * j];
        mn = fminf(mn, fminf(fminf(v[j].x, v[j].y), fminf(v[j].z, v[j].w)));
        mx = fmaxf(mx, fmaxf(fmaxf(v[j].x, v[j].y), fmaxf(v[j].z, v[j].w)));
    }
#pragma unroll
    for (int o = 16; o > 0; o >>= 1) {
        mn = fminf(mn, __shfl_xor_sync(0xffffffffu, mn, o));
        mx = fmaxf(mx, __shfl_xor_sync(0xffffffffu, mx, o));
    }
    __shared__ float smn[8], smx[8];
    if ((tid & 31) == 0) { smn[tid >> 5] = mn; smx[tid >> 5] = mx; }
    __syncthreads();
    mn = smn[0]; mx = smx[0];
#pragma unroll
    for (int w = 1; w < 8; ++w) { mn = fminf(mn, smn[w]); mx = fmaxf(mx, smx[w]); }

    const float scale = fmaxf(__fdiv_rn(mx - mn, 255.0f), 1.1920929e-07f);
    const float dmin = __fdiv_rn(mn, scale);
    const float dmax = __fdiv_rn(mx, scale);
    float zp = ((-128.0f + dmin) + (127.0f + dmax) > 0.0f) ? (-128.0f - dmin)
                                                           : (127.0f - dmax);
    zp = rintf(fminf(fmaxf(zp, -128.0f), 127.0f));

    __half* out = g_xq + (size_t)row * I_;
#pragma unroll
    for (int j = 0; j < 4; ++j) {
        float f[4] = {v[j].x, v[j].y, v[j].z, v[j].w};
        __align__(8) __half h[4];
#pragma unroll
        for (int e = 0; e < 4; ++e) {
            float q = rintf(__fdiv_rn(f[e], scale)) + zp;
            q = fminf(fmaxf(q, -128.0f), 127.0f);
            h[e] = __float2half_rn(q - zp);   // integer in [-255,255]: exact
        }
        *reinterpret_cast<uint2*>(out + (size_t)(tid + 256 * j) * 4) =
            *reinterpret_cast<const uint2*>(h);
    }
    if (tid == 0) g_sx[row] = scale;
}

// ---------------------------------------------------------------------------
// Kernel 2: groupwise int4 weight dequant -> fp16.
// ---------------------------------------------------------------------------
__global__ void __launch_bounds__(256) dequant_w_kernel(const int* __restrict__ w,
                                                        const float* __restrict__ scales,
                                                        const float* __restrict__ zeros) {
    const int t = blockIdx.x * 256 + threadIdx.x;
    const int row = t >> 9;
    const int col = (t & 511) << 3;
    const int g = col >> 8;
    const float s = scales[row * G_ + g];
    const float z = zeros[row * G_ + g];
    const int4* wp = reinterpret_cast<const int4*>(w + (size_t)row * I_ + col);
    const int4 a = wp[0], b = wp[1];
    __align__(16) __half h[8];
    h[0] = __float2half_rn(((float)a.x - z) * s);
    h[1] = __float2half_rn(((float)a.y - z) * s);
    h[2] = __float2half_rn(((float)a.z - z) * s);
    h[3] = __float2half_rn(((float)a.w - z) * s);
    h[4] = __float2half_rn(((float)b.x - z) * s);
    h[5] = __float2half_rn(((float)b.y - z) * s);
    h[6] = __float2half_rn(((float)b.z - z) * s);
    h[7] = __float2half_rn(((float)b.w - z) * s);
    *reinterpret_cast<uint4*>(g_wq + (size_t)row * I_ + col) =
        *reinterpret_cast<const uint4*>(h);
}

// ---------------------------------------------------------------------------
// Kernel 3: fp16 HMMA GEMM  C[t,o] = sx[t] * sum_k xq[t,k] * wq[o,k]
// 128x128 tile, BK=64 (128B SMEM rows, full 8-phase SW128 swizzle),
// 3-stage cp.async pipeline, 8 warps (2x4, warp tile 64x32), 2 CTAs/SM.
// ---------------------------------------------------------------------------
static constexpr int BM = 128;
static constexpr int BN = 128;
static constexpr int BK = 64;                  // halves per stage = 128B rows
static constexpr int STAGES = 3;
static constexpr int NUM_KT = I_ / BK;         // 64 iterations
static constexpr int A_ST = BM * 128;          // 16 KB (bytes)
static constexpr int ST = 2 * A_ST;            // 32 KB per stage (A+B)
static constexpr int GEMM_SMEM = STAGES * ST + 256;

// row = 0..127 (128B each), ch = 0..7 (16B chunks); full 8-phase XOR swizzle.
__device__ __forceinline__ uint32_t swz(uint32_t row, uint32_t ch) {
    return row * 128u + ((ch ^ (row & 7u)) << 4);
}

__global__ void __launch_bounds__(256, 2) gemm_kernel(float* __restrict__ C) {
    extern __shared__ char dsm[];
    const uint32_t sbase = (smem_u32(dsm) + 127u) & ~127u;

    const int tid = threadIdx.x;
    const int lane = tid & 31;
    const int wid = tid >> 5;
    const int wm = wid >> 2;      // 0..1  (64 rows each)
    const int wn = wid & 3;       // 0..3  (32 cols each)

    const int bm = blockIdx.y, bn = blockIdx.x;
    const int m0 = bm * BM, n0 = bn * BN;

    const __half* Ag = g_xq + (size_t)m0 * I_;
    const __half* Bg = g_wq + (size_t)n0 * I_;

    float acc[4][4][4];
#pragma unroll
    for (int a = 0; a < 4; ++a)
#pragma unroll
        for (int b = 0; b < 4; ++b)
#pragma unroll
            for (int c = 0; c < 4; ++c) acc[a][b][c] = 0.0f;

    // Producer: 256 threads x 8 chunks = 2048 x 16B per stage (A then B).
    auto issue_loads = [&](int s) {
        const uint32_t sa = sbase + (s % STAGES) * ST;
        const int kcol = s * BK;
#pragma unroll
        for (int i = 0; i < 8; ++i) {
            const int c = tid + i * 256;
            if (c < 1024) {                      // A: 128 rows x 8 chunks
                const int row = c >> 3, ch = c & 7;
                cp_async16(sa + swz(row, ch),
                           Ag + (size_t)row * I_ + kcol + ch * 8);
            } else {                             // B: 128 rows x 8 chunks
                const int c2 = c - 1024;
                const int row = c2 >> 3, ch = c2 & 7;
                cp_async16(sa + A_ST + swz(row, ch),
                           Bg + (size_t)row * I_ + kcol + ch * 8);
            }
        }
        cp_commit();
    };

    issue_loads(0);
    issue_loads(1);

    for (int s = 0; s < NUM_KT; ++s) {
        if (s + 2 < NUM_KT) issue_loads(s + 2);  // buf (s-1)%3: freed last iter
        else cp_commit();                        // keep group counts uniform
        cp_wait<2>();                            // stage s resident
        __syncthreads();

        const uint32_t bA = sbase + (s % STAGES) * ST;
        const uint32_t bB = bA + A_ST;

#pragma unroll
        for (int ks = 0; ks < 4; ++ks) {         // 4 x K=16 per 64-K stage
            uint32_t afr[4][4];
#pragma unroll
            for (int mi = 0; mi < 4; ++mi) {
                const uint32_t row = wm * 64 + mi * 16 + (lane & 15);
                const uint32_t ch = ks * 2 + ((lane >> 4) & 1);
                ldmatrix_x4(afr[mi], bA + swz(row, ch));
            }
            uint32_t bfr[2][4];
#pragma unroll
            for (int np = 0; np < 2; ++np) {
                const uint32_t row =
                    wn * 32 + np * 16 + (lane & 7) + (((lane >> 4) & 1) << 3);
                const uint32_t ch = ks * 2 + ((lane >> 3) & 1);
                ldmatrix_x4(bfr[np], bB + swz(row, ch));
            }
#pragma unroll
            for (int mi = 0; mi < 4; ++mi)
#pragma unroll
                for (int ni = 0; ni < 4; ++ni)
                    mma16816(acc[mi][ni], afr[mi],
                             bfr[ni >> 1][(ni & 1) * 2],
                             bfr[ni >> 1][(ni & 1) * 2 + 1]);
        }
        __syncthreads();                         // WAR guard for buf reuse
    }

    // Epilogue: y = sx[row] * acc, fp32 store
#pragma unroll
    for (int mi = 0; mi < 4; ++mi) {
        const int grow = m0 + wm * 64 + mi * 16 + (lane >> 2);
        const float s0 = g_sx[grow];
        const float s1 = g_sx[grow + 8];
#pragma unroll
        for (int ni = 0; ni < 4; ++ni) {
            const int gcol = n0 + wn * 32 + ni * 8 + (lane & 3) * 2;
            float2 v0, v1;
            v0.x = acc[mi][ni][0] * s0; v0.y = acc[mi][ni][1] * s0;
            v1.x = acc[mi][ni][2] * s1; v1.y = acc[mi][ni][3] * s1;
            *reinterpret_cast<float2*>(C + (size_t)grow * O_ + gcol) = v0;
            *reinterpret_cast<float2*>(C + (size_t)(grow + 8) * O_ + gcol) = v1;
        }
    }
}

// ---------------------------------------------------------------------------
// Launch
// ---------------------------------------------------------------------------
extern "C" void kernel_launch(void* const* d_in, const int* in_sizes, int n_in,
                              void* d_out, int out_size) {
    const float* x = (const float*)d_in[0];
    const int* w = (const int*)d_in[1];
    const float* scales = (const float*)d_in[2];
    const float* zeros = (const float*)d_in[3];
    float* out = (float*)d_out;

    static bool attr_done = false;
    if (!attr_done) {
        cudaFuncSetAttribute(gemm_kernel,
                             cudaFuncAttributeMaxDynamicSharedMemorySize,
                             GEMM_SMEM);
        attr_done = true;
    }

    quant_x_kernel<<<T_, 256>>>(x);
    dequant_w_kernel<<<(O_ * (I_ / 8)) / 256, 256>>>(w, scales, zeros);
    gemm_kernel<<<dim3(O_ / BN, T_ / BM), 256, GEMM_SMEM>>>(out);
}